// round 16
// baseline (speedup 1.0000x reference)
#include <cuda_runtime.h>
#include <cuda_fp16.h>
#include <math.h>
#include <stdint.h>

#define T 2048
#define D 1024
#define H 16
#define DH 64
#define DFF 4096
#define D3 3072

// ======================= scratch (device globals) =======================
__device__ float g_scores[(size_t)H * T * T];
__device__ float g_x[(size_t)T * D];

__device__ __half g_qin16[(size_t)T * D];
__device__ __half g_qkvwT16[(size_t)D3 * D];
__device__ __half g_qw16[(size_t)T * D];
__device__ __half g_qr16[(size_t)T * D];
__device__ __half g_k16[(size_t)T * D];
__device__ __half g_v16[(size_t)T * D];
__device__ __half g_rk16[(size_t)T * D];
__device__ __half g_pos16[(size_t)T * D];
__device__ __half g_rwT16[(size_t)D * D];
__device__ __half g_p16[(size_t)H * T * T];
__device__ __half g_vt16[(size_t)D * T];
__device__ __half g_av16[(size_t)T * D];
__device__ __half g_owT16[(size_t)D * D];
__device__ __half g_y16[(size_t)T * D];
__device__ __half g_ff16[(size_t)T * DFF];
__device__ __half g_w1T16[(size_t)DFF * D];
__device__ __half g_w2T16[(size_t)D * DFF];

// ======================= small utils =======================
__device__ __forceinline__ float warpSum(float v) {
#pragma unroll
    for (int o = 16; o > 0; o >>= 1) v += __shfl_xor_sync(0xffffffffu, v, o);
    return v;
}
__device__ __forceinline__ float warpMax(float v) {
#pragma unroll
    for (int o = 16; o > 0; o >>= 1) v = fmaxf(v, __shfl_xor_sync(0xffffffffu, v, o));
    return v;
}
__device__ __forceinline__ uint32_t h2pack(float a, float b) {
    __half2 t = __floats2half2_rn(a, b);
    return *reinterpret_cast<uint32_t*>(&t);
}
__device__ __forceinline__ uint32_t smem_u32(const void* p) {
    uint32_t a;
    asm("{ .reg .u64 tmp; cvta.to.shared.u64 tmp, %1; cvt.u32.u64 %0, tmp; }" : "=r"(a) : "l"(p));
    return a;
}

// ======================= HMMA helpers =======================
__device__ __forceinline__ void ldsm_x4(uint32_t* r, uint32_t addr) {
    asm volatile("ldmatrix.sync.aligned.m8n8.x4.shared.b16 {%0,%1,%2,%3}, [%4];"
                 : "=r"(r[0]), "=r"(r[1]), "=r"(r[2]), "=r"(r[3]) : "r"(addr));
}
__device__ __forceinline__ void mma16816h(float* c, const uint32_t* a, uint32_t b0, uint32_t b1) {
    asm volatile(
        "mma.sync.aligned.m16n8k16.row.col.f32.f16.f16.f32 "
        "{%0,%1,%2,%3}, {%4,%5,%6,%7}, {%8,%9}, {%0,%1,%2,%3};"
        : "+f"(c[0]), "+f"(c[1]), "+f"(c[2]), "+f"(c[3])
        : "r"(a[0]), "r"(a[1]), "r"(a[2]), "r"(a[3]), "r"(b0), "r"(b1));
}
#define MMSTRIDE 72
__device__ __forceinline__ uint32_t faddr(uint32_t base, int row0, int kk, int lane) {
    return base + (uint32_t)(((row0 + (lane & 15)) * MMSTRIDE + kk * 16 + ((lane >> 4) << 3)) * 2);
}
__device__ __forceinline__ void cpa16(uint32_t dst, const void* src) {
    asm volatile("cp.async.cg.shared.global [%0], [%1], 16;"
                 :: "r"(dst), "l"(__cvta_generic_to_global(src)) : "memory");
}
__device__ __forceinline__ void cpa16z(uint32_t dst, const void* src, int bytes) {
    asm volatile("cp.async.cg.shared.global [%0], [%1], 16, %2;"
                 :: "r"(dst), "l"(__cvta_generic_to_global(src)), "r"(bytes) : "memory");
}

// ======================= convert kernels =======================
__global__ void splitcvt16_kernel(const float* __restrict__ x, __half* __restrict__ o16, int n) {
    int i = (blockIdx.x * 256 + threadIdx.x) * 4;
    if (i >= n) return;
    float4 v = *(const float4*)(x + i);
    uint2 o;
    o.x = h2pack(v.x, v.y);
    o.y = h2pack(v.z, v.w);
    *(uint2*)&o16[i] = o;
}

__global__ void wconvT16_kernel(const float* __restrict__ W, __half* __restrict__ th,
                                int K, int N) {
    __shared__ float sm[32][33];
    const int k0 = blockIdx.y * 32, n0 = blockIdx.x * 32;
    const int tx = threadIdx.x, ty = threadIdx.y;
    const int t = ty * 32 + tx;
#pragma unroll
    for (int i = 0; i < 4; i++)
        sm[ty + 8 * i][tx] = W[(size_t)(k0 + ty + 8 * i) * N + n0 + tx];
    __syncthreads();
#pragma unroll
    for (int e = 0; e < 2; e++) {
        int pid = e * 256 + t;
        int n = pid >> 4, kp = pid & 15;
        *(uint32_t*)&th[(size_t)(n0 + n) * K + k0 + 2 * kp] =
            h2pack(sm[2 * kp][n], sm[2 * kp + 1][n]);
    }
}

__global__ void vconvT16h_kernel(const __half* __restrict__ v16, __half* __restrict__ th) {
    __shared__ float sm[32][33];
    const int t0 = blockIdx.x * 32, c0 = blockIdx.y * 32;
    const int tx = threadIdx.x, ty = threadIdx.y;
    const int t = ty * 32 + tx;
#pragma unroll
    for (int i = 0; i < 4; i++)
        sm[ty + 8 * i][tx] = __half2float(v16[(size_t)(t0 + ty + 8 * i) * D + c0 + tx]);
    __syncthreads();
#pragma unroll
    for (int e = 0; e < 2; e++) {
        int pid = e * 256 + t;
        int c = pid >> 4, tp = pid & 15;
        *(uint32_t*)&th[(size_t)(c0 + c) * T + t0 + 2 * tp] =
            h2pack(sm[2 * tp][c], sm[2 * tp + 1][c]);
    }
}

// ======================= layernorm -> fp16 =======================
__global__ void ln16_kernel(const float* __restrict__ x, const float* __restrict__ g,
                            const float* __restrict__ b, __half* __restrict__ o16) {
    const int row = blockIdx.x;
    const int t = threadIdx.x;
    const float* xr = x + (size_t)row * D;
    float4 v = *(const float4*)&xr[t * 4];
    float s = v.x + v.y + v.z + v.w;
    __shared__ float red1[8], red2[8];
    s = warpSum(s);
    if ((t & 31) == 0) red1[t >> 5] = s;
    __syncthreads();
    float tot = red1[0] + red1[1] + red1[2] + red1[3] + red1[4] + red1[5] + red1[6] + red1[7];
    const float mean = tot * (1.0f / D);
    float dx = v.x - mean, dy = v.y - mean, dz = v.z - mean, dw = v.w - mean;
    float s2 = dx * dx + dy * dy + dz * dz + dw * dw;
    s2 = warpSum(s2);
    if ((t & 31) == 0) red2[t >> 5] = s2;
    __syncthreads();
    float var = (red2[0] + red2[1] + red2[2] + red2[3] + red2[4] + red2[5] + red2[6] + red2[7]) * (1.0f / D);
    const float inv = rsqrtf(var + 1e-5f);
    float4 gg = *(const float4*)&g[t * 4];
    float4 bb = *(const float4*)&b[t * 4];
    uint2 o;
    o.x = h2pack(dx * inv * gg.x + bb.x, dy * inv * gg.y + bb.y);
    o.y = h2pack(dz * inv * gg.z + bb.z, dw * inv * gg.w + bb.w);
    *(uint2*)&o16[(size_t)row * D + t * 4] = o;
}

// ======================= fp16 1-term GEMM: 128x128 tile, 3-stage, 2 CTAs/SM ===
// EPI bits: 1=bias, 2=relu, 4=residual, 8=fp16-out
#define H_ARR (128 * MMSTRIDE * 2)
#define H_STAGE (2 * H_ARR)                 // 36864
#define MMH_SMEM (3 * H_STAGE)              // 110592

__device__ __forceinline__ void mmh_load_chunk(
    const __half* __restrict__ A, const __half* __restrict__ B,
    int m0, int n0, int K, int t, uint32_t stage_base, int tid) {
    const size_t k0 = (size_t)t * 64;
#pragma unroll
    for (int e = 0; e < 8; e++) {
        int idx = e * 256 + tid;
        int arr = idx >> 10;
        int row = (idx >> 3) & 127;
        int ck  = idx & 7;
        const __half* src = (arr == 0 ? A + (size_t)(m0 + row) * K
                                      : B + (size_t)(n0 + row) * K) + k0 + ck * 8;
        cpa16(stage_base + (uint32_t)arr * H_ARR + (uint32_t)(row * 144 + ck * 16), src);
    }
    asm volatile("cp.async.commit_group;" ::: "memory");
}

template <int EPI>
__global__ void __launch_bounds__(256, 2) mmh_kernel(
    const __half* __restrict__ A, const __half* __restrict__ B,
    const float* __restrict__ bias, const float* __restrict__ Rm,
    float* __restrict__ Cf, __half* __restrict__ C16,
    int M, int N, int K) {
    extern __shared__ char smem[];
    const uint32_t sbase = smem_u32(smem);
    const int tid = threadIdx.x;
    const int wid = tid >> 5, lane = tid & 31;
    const int m0 = blockIdx.y * 128, n0 = blockIdx.x * 128;
    const int mrow = (wid & 3) * 32;
    const int nrow = (wid >> 2) * 64;

    float c[2][8][4] = {};
    const int nch = K / 64;

    mmh_load_chunk(A, B, m0, n0, K, 0, sbase, tid);
    if (nch > 1) mmh_load_chunk(A, B, m0, n0, K, 1, sbase + H_STAGE, tid);

    int st = 0;
    for (int t = 0; t < nch; t++) {
        if (t + 1 < nch) { asm volatile("cp.async.wait_group 1;" ::: "memory"); }
        else             { asm volatile("cp.async.wait_group 0;" ::: "memory"); }
        __syncthreads();
        if (t + 2 < nch) {
            int ldst = st + 2; if (ldst >= 3) ldst -= 3;
            mmh_load_chunk(A, B, m0, n0, K, t + 2, sbase + (uint32_t)ldst * H_STAGE, tid);
        }
        const uint32_t sb = sbase + (uint32_t)st * H_STAGE;
        const uint32_t vb = sb + H_ARR;
#pragma unroll
        for (int kk = 0; kk < 4; kk++) {
            uint32_t a[2][4], b[4][4];
            ldsm_x4(a[0], faddr(sb, mrow,      kk, lane));
            ldsm_x4(a[1], faddr(sb, mrow + 16, kk, lane));
#pragma unroll
            for (int nf = 0; nf < 4; nf++)
                ldsm_x4(b[nf], faddr(vb, nrow + nf * 16, kk, lane));
#pragma unroll
            for (int mi = 0; mi < 2; mi++)
#pragma unroll
                for (int nb = 0; nb < 8; nb++) {
                    const int nf = nb >> 1, o = nb & 1;
                    mma16816h(c[mi][nb], a[mi], b[nf][o], b[nf][2 + o]);
                }
        }
        if (++st == 3) st = 0;
    }

    const int tq = lane >> 2, tr = lane & 3;
#pragma unroll
    for (int mi = 0; mi < 2; mi++)
#pragma unroll
        for (int nb = 0; nb < 8; nb++)
#pragma unroll
            for (int hh = 0; hh < 2; hh++) {
                int gr = m0 + mrow + mi * 16 + tq + hh * 8;
                int gc = n0 + nrow + nb * 8 + tr * 2;
                float v0 = c[mi][nb][hh * 2 + 0];
                float v1 = c[mi][nb][hh * 2 + 1];
                if (EPI & 1) { v0 += bias[gc]; v1 += bias[gc + 1]; }
                if (EPI & 2) { v0 = fmaxf(v0, 0.f); v1 = fmaxf(v1, 0.f); }
                if (EPI & 4) {
                    float2 r = *(const float2*)&Rm[(size_t)gr * N + gc];
                    v0 += r.x; v1 += r.y;
                }
                if (EPI & 8) {
                    *(uint32_t*)&C16[(size_t)gr * N + gc] = h2pack(v0, v1);
                } else {
                    float2 o; o.x = v0; o.y = v1;
                    *(float2*)&Cf[(size_t)gr * N + gc] = o;
                }
            }
}

// ======================= fp16 QKV GEMM with attn-prep epilogue (3-stage) ======
__global__ void __launch_bounds__(256, 2) mmqkv16_kernel(
    const __half* __restrict__ A, const __half* __restrict__ B,
    const float* __restrict__ rwb, const float* __restrict__ rrb,
    __half* __restrict__ qw16, __half* __restrict__ qr16,
    __half* __restrict__ k16, __half* __restrict__ v16,
    int M, int N, int K) {
    extern __shared__ char smem[];
    const uint32_t sbase = smem_u32(smem);
    const int tid = threadIdx.x;
    const int wid = tid >> 5, lane = tid & 31;
    const int m0 = blockIdx.y * 128, n0 = blockIdx.x * 128;
    const int mrow = (wid & 3) * 32;
    const int nrow = (wid >> 2) * 64;

    float c[2][8][4] = {};
    const int nch = K / 64;

    mmh_load_chunk(A, B, m0, n0, K, 0, sbase, tid);
    if (nch > 1) mmh_load_chunk(A, B, m0, n0, K, 1, sbase + H_STAGE, tid);

    int st = 0;
    for (int t = 0; t < nch; t++) {
        if (t + 1 < nch) { asm volatile("cp.async.wait_group 1;" ::: "memory"); }
        else             { asm volatile("cp.async.wait_group 0;" ::: "memory"); }
        __syncthreads();
        if (t + 2 < nch) {
            int ldst = st + 2; if (ldst >= 3) ldst -= 3;
            mmh_load_chunk(A, B, m0, n0, K, t + 2, sbase + (uint32_t)ldst * H_STAGE, tid);
        }
        const uint32_t sb = sbase + (uint32_t)st * H_STAGE;
        const uint32_t vb = sb + H_ARR;
#pragma unroll
        for (int kk = 0; kk < 4; kk++) {
            uint32_t a[2][4], b[4][4];
            ldsm_x4(a[0], faddr(sb, mrow,      kk, lane));
            ldsm_x4(a[1], faddr(sb, mrow + 16, kk, lane));
#pragma unroll
            for (int nf = 0; nf < 4; nf++)
                ldsm_x4(b[nf], faddr(vb, nrow + nf * 16, kk, lane));
#pragma unroll
            for (int mi = 0; mi < 2; mi++)
#pragma unroll
                for (int nb = 0; nb < 8; nb++) {
                    const int nf = nb >> 1, o = nb & 1;
                    mma16816h(c[mi][nb], a[mi], b[nf][o], b[nf][2 + o]);
                }
        }
        if (++st == 3) st = 0;
    }

    const int tq = lane >> 2, tr = lane & 3;
#pragma unroll
    for (int mi = 0; mi < 2; mi++)
#pragma unroll
        for (int nb = 0; nb < 8; nb++)
#pragma unroll
            for (int hh = 0; hh < 2; hh++) {
                int gr = m0 + mrow + mi * 16 + tq + hh * 8;
                int gc = n0 + nrow + nb * 8 + tr * 2;
                float v0 = c[mi][nb][hh * 2 + 0];
                float v1 = c[mi][nb][hh * 2 + 1];
                if (gc < D) {
                    size_t o = (size_t)gr * D + gc;
                    *(uint32_t*)&qw16[o] = h2pack(v0 + rwb[gc], v1 + rwb[gc + 1]);
                    *(uint32_t*)&qr16[o] = h2pack(v0 + rrb[gc], v1 + rrb[gc + 1]);
                } else if (gc < 2 * D) {
                    *(uint32_t*)&k16[(size_t)gr * D + gc - D] = h2pack(v0, v1);
                } else {
                    *(uint32_t*)&v16[(size_t)gr * D + gc - 2 * D] = h2pack(v0, v1);
                }
            }
}

// ======================= fp16 1-term attention scores (unchanged) ============
#define SAH 18432
#define SCH_BAND (3 * SAH)          // 55296
#define SCH_SMEM (3 * SAH + 36864)  // 92160

__global__ void __launch_bounds__(256, 2) scores16_kernel(
    const __half* __restrict__ qw, const __half* __restrict__ qr,
    const __half* __restrict__ k,  const __half* __restrict__ rk,
    float* __restrict__ sc) {
    const int h = blockIdx.z;
    const int n = blockIdx.x;
    float rf = (sqrtf(8.f * n + 1.f) - 1.f) * 0.5f;
    int iT = (int)rf;
    if ((iT + 1) * (iT + 2) / 2 <= n) iT++;
    if (iT * (iT + 1) / 2 > n) iT--;
    const int jT = n - iT * (iT + 1) / 2;
    const int i0 = iT * 128, j0 = jT * 128;
    extern __shared__ char smem[];
    const uint32_t sb = smem_u32(smem);
    const int tid = threadIdx.x;
    const int wid = tid >> 5, lane = tid & 31;
    const int mrow = (wid & 3) * 32;
    const int nrowAC = (wid >> 2) * 64;
    const int nrowQ  = (wid >> 2) * 32;
    const int pbase = T - 1 - i0 + j0 - 127;
    float* bdbuf = (float*)(smem);

#pragma unroll
    for (int e = 0; e < 12; e++) {
        int idx = e * 256 + tid;
        int arr = idx >> 10;                // 0: qw, 1: k, 2: qr
        int row = (idx >> 3) & 127;
        int ck  = idx & 7;
        const __half* src = (arr == 0) ? qw : (arr == 1) ? k : qr;
        int grow = ((arr == 1) ? j0 : i0) + row;
        cpa16(sb + (uint32_t)arr * SAH + (uint32_t)(row * 144 + ck * 16),
              src + (size_t)grow * D + h * DH + ck * 8);
    }
    asm volatile("cp.async.commit_group;" ::: "memory");
#pragma unroll
    for (int e = 0; e < 8; e++) {
        int idx = e * 256 + tid;
        int row = (idx >> 3) & 255;
        int ck  = idx & 7;
        int p = pbase + row;
        bool valid = (p >= 0 && p < T);
        size_t off = valid ? ((size_t)p * D + h * DH + ck * 8) : 0;
        cpa16z(sb + SCH_BAND + (uint32_t)(row * 144 + ck * 16), rk + off, valid ? 16 : 0);
    }
    asm volatile("cp.async.commit_group;" ::: "memory");
    asm volatile("cp.async.wait_group 1;" ::: "memory");
    __syncthreads();

    float acc[2][8][4] = {};
#pragma unroll
    for (int kk = 0; kk < 4; kk++) {
        uint32_t a[2][4], b[4][4];
        ldsm_x4(a[0], faddr(sb, mrow,      kk, lane));
        ldsm_x4(a[1], faddr(sb, mrow + 16, kk, lane));
#pragma unroll
        for (int nf = 0; nf < 4; nf++)
            ldsm_x4(b[nf], faddr(sb + SAH, nrowAC + nf * 16, kk, lane));
#pragma unroll
        for (int mi = 0; mi < 2; mi++)
#pragma unroll
            for (int nb = 0; nb < 8; nb++) {
                const int nf = nb >> 1, o = nb & 1;
                mma16816h(acc[mi][nb], a[mi], b[nf][o], b[nf][2 + o]);
            }
    }
    asm volatile("cp.async.wait_group 0;" ::: "memory");
    __syncthreads();

    const int tq = lane >> 2, tr = lane & 3;
#pragma unroll 1
    for (int q = 0; q < 4; q++) {
        float c2[2][4][4] = {};
#pragma unroll
        for (int kk = 0; kk < 4; kk++) {
            uint32_t a[2][4], b[2][4];
            ldsm_x4(a[0], faddr(sb + 2 * SAH, mrow,      kk, lane));
            ldsm_x4(a[1], faddr(sb + 2 * SAH, mrow + 16, kk, lane));
            ldsm_x4(b[0], faddr(sb + SCH_BAND, q * 64 + nrowQ,      kk, lane));
            ldsm_x4(b[1], faddr(sb + SCH_BAND, q * 64 + nrowQ + 16, kk, lane));
#pragma unroll
            for (int mi = 0; mi < 2; mi++)
#pragma unroll
                for (int nb = 0; nb < 4; nb++) {
                    const int nf = nb >> 1, o = nb & 1;
                    mma16816h(c2[mi][nb], a[mi], b[nf][o], b[nf][2 + o]);
                }
        }
        __syncthreads();
#pragma unroll
        for (int mi = 0; mi < 2; mi++)
#pragma unroll
            for (int nb = 0; nb < 4; nb++)
#pragma unroll
                for (int hh = 0; hh < 2; hh++) {
                    int di = mrow + mi * 16 + tq + hh * 8;
                    int djq = nrowQ + nb * 8 + tr * 2;
                    bdbuf[di * 66 + djq]     = c2[mi][nb][hh * 2 + 0];
                    bdbuf[di * 66 + djq + 1] = c2[mi][nb][hh * 2 + 1];
                }
        __syncthreads();
#pragma unroll
        for (int mi = 0; mi < 2; mi++)
#pragma unroll
            for (int nb = 0; nb < 8; nb++)
#pragma unroll
                for (int hh = 0; hh < 2; hh++) {
                    int di = mrow + mi * 16 + tq + hh * 8;
                    int dj = nrowAC + nb * 8 + tr * 2;
#pragma unroll
                    for (int cc = 0; cc < 2; cc++) {
                        int pl = 127 + (dj + cc) - di;
                        if ((pl >> 6) == q)
                            acc[mi][nb][hh * 2 + cc] += bdbuf[di * 66 + (pl & 63)];
                    }
                }
        __syncthreads();
    }

    const float scale = 0.125f;
#pragma unroll
    for (int mi = 0; mi < 2; mi++)
#pragma unroll
        for (int nb = 0; nb < 8; nb++)
#pragma unroll
            for (int hh = 0; hh < 2; hh++) {
                int gi = i0 + mrow + mi * 16 + tq + hh * 8;
                int gj = j0 + nrowAC + nb * 8 + tr * 2;
                float2 o;
                o.x = acc[mi][nb][hh * 2 + 0] * scale;
                o.y = acc[mi][nb][hh * 2 + 1] * scale;
                *(float2*)&sc[((size_t)h * T + gi) * T + gj] = o;
            }
}

// ======================= causal softmax -> fp16 probs (pad to 128) ===========
__global__ void softmax_kernel(const float* __restrict__ sc, __half* __restrict__ p16) {
    const int i = blockIdx.x;
    const int h = blockIdx.y;
    const size_t roff = ((size_t)h * T + i) * T;
    const float* row = sc + roff;
    const int t = threadIdx.x;
    const int n = i + 1;
    const int nup = (i & ~127) + 128;
    float4 v[2];
    float mx = -3.4e38f;
#pragma unroll
    for (int p = 0; p < 2; p++) {
        int j = (p * 256 + t) * 4;
        if (j < nup) {
            float4 w = *(const float4*)(row + j);
            w.x = (j + 0 < n) ? w.x : -3.4e38f;
            w.y = (j + 1 < n) ? w.y : -3.4e38f;
            w.z = (j + 2 < n) ? w.z : -3.4e38f;
            w.w = (j + 3 < n) ? w.w : -3.4e38f;
            v[p] = w;
            mx = fmaxf(mx, fmaxf(fmaxf(w.x, w.y), fmaxf(w.z, w.w)));
        } else {
            v[p].x = v[p].y = v[p].z = v[p].w = -3.4e38f;
        }
    }
    __shared__ float red1[8], red2[8];
    mx = warpMax(mx);
    if ((t & 31) == 0) red1[t >> 5] = mx;
    __syncthreads();
    mx = fmaxf(fmaxf(fmaxf(red1[0], red1[1]), fmaxf(red1[2], red1[3])),
               fmaxf(fmaxf(red1[4], red1[5]), fmaxf(red1[6], red1[7])));
    float s = 0.f;
#pragma unroll
    for (int p = 0; p < 2; p++) {
        float e0 = (v[p].x > -3.0e38f) ? __expf(v[p].x - mx) : 0.f;
        float e1 = (v[p].y > -3.0e38f) ? __expf(v[p].y - mx) : 0.f;
        float e2 = (v[p].z > -3.0e38f) ? __expf(v[p].z - mx) : 0.f;
        float e3 = (v[p].w > -3.0e38f) ? __expf(v[p].w - mx) : 0.f;
        v[p].x = e0; v[p].y = e1; v[p].z = e2; v[p].w = e3;
        s += e0 + e1 + e2 + e3;
    }
    s = warpSum(s);
    if ((t & 31) == 0) red2[t >> 5] = s;
    __syncthreads();
    float tot = red2[0] + red2[1] + red2[2] + red2[3] + red2[4] + red2[5] + red2[6] + red2[7];
    float inv = 1.0f / tot;
#pragma unroll
    for (int p = 0; p < 2; p++) {
        int j = (p * 256 + t) * 4;
        if (j < nup) {
            uint2 pu;
            pu.x = h2pack(v[p].x * inv, v[p].y * inv);
            pu.y = h2pack(v[p].z * inv, v[p].w * inv);
            *(uint2*)&p16[roff + j] = pu;
        }
    }
}

// ======================= probs layout: fp16 [h][i][j] -> f32 [i][j][h] ========
__global__ void probs_out_kernel(const __half* __restrict__ p16,
                                 float* __restrict__ out) {
    const int i = blockIdx.y;
    const int t = threadIdx.x;
    const int nup = (i & ~63) + 64;
    __shared__ float sm[16][66];
#pragma unroll 1
    for (int s = 0; s < 4; s++) {
        const int j0 = (blockIdx.x * 4 + s) * 64;
        float* dst = out + ((size_t)i * T + j0) * H;
        if (j0 < nup) {
#pragma unroll
            for (int e = 0; e < 2; e++) {
                int idx = e * 256 + t;
                int hh = idx >> 5, jp = idx & 31;
                size_t o = ((size_t)hh * T + i) * T + j0 + jp * 2;
                __half2 a = *(const __half2*)&p16[o];
                sm[hh][jp * 2]     = __half2float(a.x);
                sm[hh][jp * 2 + 1] = __half2float(a.y);
            }
            __syncthreads();
            int base = t * 4;
            float4 o4;
            o4.x = sm[(base + 0) & 15][(base + 0) >> 4];
            o4.y = sm[(base + 1) & 15][(base + 1) >> 4];
            o4.z = sm[(base + 2) & 15][(base + 2) >> 4];
            o4.w = sm[(base + 3) & 15][(base + 3) >> 4];
            *(float4*)&dst[base] = o4;
            __syncthreads();
        } else {
            float4 z; z.x = z.y = z.z = z.w = 0.f;
            *(float4*)&dst[t * 4] = z;
        }
    }
}

// ======================= fp16 PV (3-stage) =======================
#define PVH_PARR 18432
#define PVH_VARR 9216
#define PVH_STAGE (PVH_PARR + PVH_VARR)     // 27648
#define PVH_SMEM (3 * PVH_STAGE)            // 82944

__device__ __forceinline__ void pvh_load_chunk(
    const __half* __restrict__ P, const __half* __restrict__ V,
    int h, int i0, int t, uint32_t stage_base, int tid) {
    const size_t j0 = (size_t)t * 64;
#pragma unroll
    for (int e = 0; e < 6; e++) {
        int idx = e * 256 + tid;
        const __half* src;
        uint32_t dst;
        if (idx < 1024) {
            int row = (idx >> 3) & 127;
            int ck  = idx & 7;
            src = P + ((size_t)h * T + i0 + row) * T + j0 + ck * 8;
            dst = stage_base + (uint32_t)(row * 144 + ck * 16);
        } else {
            int k = idx - 1024;
            int row = (k >> 3) & 63;
            int ck  = k & 7;
            src = V + (size_t)(h * DH + row) * T + j0 + ck * 8;
            dst = stage_base + PVH_PARR + (uint32_t)(row * 144 + ck * 16);
        }
        cpa16(dst, src);
    }
    asm volatile("cp.async.commit_group;" ::: "memory");
}

__global__ void __launch_bounds__(256, 2) pv16_kernel(
    const __half* __restrict__ P, const __half* __restrict__ V,
    __half* __restrict__ av16) {
    extern __shared__ char smem[];
    const uint32_t sbase = smem_u32(smem);
    const int h = blockIdx.y;
    const int i0 = (gridDim.x - 1 - blockIdx.x) * 128;
    const int tid = threadIdx.x;
    const int wid = tid >> 5, lane = tid & 31;
    const int mrow = (wid & 3) * 32;
    const int nrow = (wid >> 2) * 32;

    float c[2][4][4] = {};
    const int nch = i0 / 64 + 2;

    pvh_load_chunk(P, V, h, i0, 0, sbase, tid);
    if (nch > 1) pvh_load_chunk(P, V, h, i0, 1, sbase + PVH_STAGE, tid);

    int st = 0;
    for (int t = 0; t < nch; t++) {
        if (t + 1 < nch) { asm volatile("cp.async.wait_group 1;" ::: "memory"); }
        else             { asm volatile("cp.async.wait_group 0;" ::: "memory"); }
        __syncthreads();
        if (t + 2 < nch) {
            int ldst = st + 2; if (ldst >= 3) ldst -= 3;
            pvh_load_chunk(P, V, h, i0, t + 2, sbase + (uint32_t)ldst * PVH_STAGE, tid);
        }
        const uint32_t sb = sbase + (uint32_t)st * PVH_STAGE;
        const uint32_t vb = sb + PVH_PARR;
#pragma unroll
        for (int kk = 0; kk < 4; kk++) {
            uint32_t a[2][4], b[2][4];
            ldsm_x4(a[0], faddr(sb, mrow,      kk, lane));
            ldsm_x4(a[1], faddr(sb, mrow + 16, kk, lane));
            ldsm_x4(b[0], faddr(vb, nrow,      kk, lane));
            ldsm_x4(b[1], faddr(vb, nrow + 16, kk, lane));
#pragma unroll
            for (int mi = 0; mi < 2; mi++)
#pragma unroll
                for (int nb = 0; nb < 4; nb++) {
                    const int nf = nb >> 1, o = nb & 1;
                    mma16816h(c[mi][nb], a[mi], b[nf][o], b[nf][2 + o]);
                }
        }
        if (++st == 3) st = 0;
    }

    const int tq = lane >> 2, tr = lane & 3;
#pragma unroll
    for (int mi = 0; mi < 2; mi++)
#pragma unroll
        for (int nb = 0; nb < 4; nb++)
#pragma unroll
            for (int hh = 0; hh < 2; hh++) {
                int gi = i0 + mrow + mi * 16 + tq + hh * 8;
                int gd = nrow + nb * 8 + tr * 2;
                size_t o = (size_t)gi * D + h * DH + gd;
                *(uint32_t*)&av16[o] = h2pack(c[mi][nb][hh * 2 + 0], c[mi][nb][hh * 2 + 1]);
            }
}

// ======================= host launch =======================
extern "C" void kernel_launch(void* const* d_in, const int* in_sizes, int n_in,
                              void* d_out, int out_size) {
    const float* input = (const float*)d_in[0];
    const float* pos   = (const float*)d_in[1];
    const float* rwb   = (const float*)d_in[2];
    const float* rrb   = (const float*)d_in[3];
    const float* ln1g  = (const float*)d_in[5];
    const float* ln1b  = (const float*)d_in[6];
    const float* qkvw  = (const float*)d_in[7];
    const float* rw    = (const float*)d_in[8];
    const float* ow    = (const float*)d_in[9];
    const float* ln2g  = (const float*)d_in[10];
    const float* ln2b  = (const float*)d_in[11];
    const float* ffw1  = (const float*)d_in[12];
    const float* ffb1  = (const float*)d_in[13];
    const float* ffw2  = (const float*)d_in[14];
    const float* ffb2  = (const float*)d_in[15];
    float* out = (float*)d_out;

    float *scores, *x;
    cudaGetSymbolAddress((void**)&scores, g_scores);
    cudaGetSymbolAddress((void**)&x,      g_x);
    __half *qin16, *qkvwT16, *qw16, *qr16, *k16, *v16, *rk16, *pos16, *rwT16;
    cudaGetSymbolAddress((void**)&qin16,   g_qin16);
    cudaGetSymbolAddress((void**)&qkvwT16, g_qkvwT16);
    cudaGetSymbolAddress((void**)&qw16, g_qw16);
    cudaGetSymbolAddress((void**)&qr16, g_qr16);
    cudaGetSymbolAddress((void**)&k16,  g_k16);
    cudaGetSymbolAddress((void**)&v16,  g_v16);
    cudaGetSymbolAddress((void**)&rk16, g_rk16);
    cudaGetSymbolAddress((void**)&pos16, g_pos16);
    cudaGetSymbolAddress((void**)&rwT16, g_rwT16);
    __half *p16, *vt16, *av16, *owT16, *y16, *ff16, *w1T16, *w2T16;
    cudaGetSymbolAddress((void**)&p16,   g_p16);
    cudaGetSymbolAddress((void**)&vt16,  g_vt16);
    cudaGetSymbolAddress((void**)&av16,  g_av16);
    cudaGetSymbolAddress((void**)&owT16, g_owT16);
    cudaGetSymbolAddress((void**)&y16,   g_y16);
    cudaGetSymbolAddress((void**)&ff16,  g_ff16);
    cudaGetSymbolAddress((void**)&w1T16, g_w1T16);
    cudaGetSymbolAddress((void**)&w2T16, g_w2T16);

    cudaFuncSetAttribute((const void*)mmqkv16_kernel, cudaFuncAttributeMaxDynamicSharedMemorySize, MMH_SMEM);
    cudaFuncSetAttribute((const void*)mmh_kernel<4>,  cudaFuncAttributeMaxDynamicSharedMemorySize, MMH_SMEM);
    cudaFuncSetAttribute((const void*)mmh_kernel<8>,  cudaFuncAttributeMaxDynamicSharedMemorySize, MMH_SMEM);
    cudaFuncSetAttribute((const void*)mmh_kernel<11>, cudaFuncAttributeMaxDynamicSharedMemorySize, MMH_SMEM);
    cudaFuncSetAttribute((const void*)mmh_kernel<5>,  cudaFuncAttributeMaxDynamicSharedMemorySize, MMH_SMEM);
    cudaFuncSetAttribute((const void*)scores16_kernel, cudaFuncAttributeMaxDynamicSharedMemorySize, SCH_SMEM);
    cudaFuncSetAttribute((const void*)pv16_kernel,  cudaFuncAttributeMaxDynamicSharedMemorySize, PVH_SMEM);

    const dim3 wthr(32, 8);
    const bool probs_fit =
        (long long)out_size >= (long long)T * D + (long long)H * T * T;

    ln16_kernel<<<T, 256>>>(input, ln1g, ln1b, qin16);                               // 0
    wconvT16_kernel<<<dim3(D3 / 32, D / 32), wthr>>>(qkvw, qkvwT16, D, D3);          // 1
    splitcvt16_kernel<<<(T * D) / 1024, 256>>>(pos, pos16, T * D);                   // 2
    mmqkv16_kernel<<<dim3(D3 / 128, T / 128), 256, MMH_SMEM>>>(                       // 3 (profiled)
        qin16, qkvwT16, rwb, rrb, qw16, qr16, k16, v16, T, D3, D);
    wconvT16_kernel<<<dim3(D / 32,  D / 32), wthr>>>(rw, rwT16, D, D);               // 4
    vconvT16h_kernel<<<dim3(T / 32, D / 32), wthr>>>(v16, vt16);                     // 5
    mmh_kernel<8><<<dim3(D / 128, T / 128), 256, MMH_SMEM>>>(                         // 6: rk
        pos16, rwT16, nullptr, nullptr, nullptr, rk16, T, D, D);
    wconvT16_kernel<<<dim3(D / 32,  D / 32), wthr>>>(ow, owT16, D, D);               // 7
    scores16_kernel<<<dim3(136, 1, H), 256, SCH_SMEM>>>(qw16, qr16, k16, rk16, scores);
    softmax_kernel<<<dim3(T, H), 256>>>(scores, p16);
    if (probs_fit) {
        probs_out_kernel<<<dim3(T / 256, T), 256>>>(p16, out + (size_t)T * D);
    }
    pv16_kernel<<<dim3(T / 128, H), 256, PVH_SMEM>>>(p16, vt16, av16);
    mmh_kernel<4><<<dim3(D / 128, T / 128), 256, MMH_SMEM>>>(
        av16, owT16, nullptr, input, x, nullptr, T, D, D);
    ln16_kernel<<<T, 256>>>(x, ln2g, ln2b, y16);
    wconvT16_kernel<<<dim3(DFF / 32, D / 32), wthr>>>(ffw1, w1T16, D, DFF);
    wconvT16_kernel<<<dim3(D / 32, DFF / 32), wthr>>>(ffw2, w2T16, DFF, D);
    mmh_kernel<11><<<dim3(DFF / 128, T / 128), 256, MMH_SMEM>>>(
        y16, w1T16, ffb1, nullptr, nullptr, ff16, T, DFF, D);
    mmh_kernel<5><<<dim3(D / 128, T / 128), 256, MMH_SMEM>>>(
        ff16, w2T16, ffb2, x, out, nullptr, T, D, DFF);
}

// round 17
// speedup vs baseline: 1.0208x; 1.0208x over previous
#include <cuda_runtime.h>
#include <cuda_fp16.h>
#include <math.h>
#include <stdint.h>

#define T 2048
#define D 1024
#define H 16
#define DH 64
#define DFF 4096
#define D3 3072

// ======================= scratch (device globals) =======================
__device__ float g_scores[(size_t)H * T * T];
__device__ float g_x[(size_t)T * D];

__device__ __half g_qin16[(size_t)T * D];
__device__ __half g_qkvwT16[(size_t)D3 * D];
__device__ __half g_qw16[(size_t)T * D];
__device__ __half g_qr16[(size_t)T * D];
__device__ __half g_k16[(size_t)T * D];
__device__ __half g_v16[(size_t)T * D];
__device__ __half g_rk16[(size_t)T * D];
__device__ __half g_pos16[(size_t)T * D];
__device__ __half g_rwT16[(size_t)D * D];
__device__ __half g_p16[(size_t)H * T * T];
__device__ __half g_vt16[(size_t)D * T];
__device__ __half g_av16[(size_t)T * D];
__device__ __half g_owT16[(size_t)D * D];
__device__ __half g_y16[(size_t)T * D];
__device__ __half g_ff16[(size_t)T * DFF];
__device__ __half g_w1T16[(size_t)DFF * D];
__device__ __half g_w2T16[(size_t)D * DFF];

// ======================= small utils =======================
__device__ __forceinline__ float warpSum(float v) {
#pragma unroll
    for (int o = 16; o > 0; o >>= 1) v += __shfl_xor_sync(0xffffffffu, v, o);
    return v;
}
__device__ __forceinline__ float warpMax(float v) {
#pragma unroll
    for (int o = 16; o > 0; o >>= 1) v = fmaxf(v, __shfl_xor_sync(0xffffffffu, v, o));
    return v;
}
__device__ __forceinline__ uint32_t h2pack(float a, float b) {
    __half2 t = __floats2half2_rn(a, b);
    return *reinterpret_cast<uint32_t*>(&t);
}
__device__ __forceinline__ uint32_t smem_u32(const void* p) {
    uint32_t a;
    asm("{ .reg .u64 tmp; cvta.to.shared.u64 tmp, %1; cvt.u32.u64 %0, tmp; }" : "=r"(a) : "l"(p));
    return a;
}
// streaming (evict-first) stores/loads for write-once / read-once data
__device__ __forceinline__ void stg_cs_f2(float* p, float2 v) {
    asm volatile("st.global.cs.v2.f32 [%0], {%1, %2};" :: "l"(p), "f"(v.x), "f"(v.y) : "memory");
}
__device__ __forceinline__ void stg_cs_f4(float* p, float4 v) {
    asm volatile("st.global.cs.v4.f32 [%0], {%1, %2, %3, %4};"
                 :: "l"(p), "f"(v.x), "f"(v.y), "f"(v.z), "f"(v.w) : "memory");
}
__device__ __forceinline__ float4 ldg_cs_f4(const float* p) {
    float4 v;
    asm volatile("ld.global.cs.v4.f32 {%0, %1, %2, %3}, [%4];"
                 : "=f"(v.x), "=f"(v.y), "=f"(v.z), "=f"(v.w) : "l"(p));
    return v;
}

// ======================= HMMA helpers =======================
__device__ __forceinline__ void ldsm_x4(uint32_t* r, uint32_t addr) {
    asm volatile("ldmatrix.sync.aligned.m8n8.x4.shared.b16 {%0,%1,%2,%3}, [%4];"
                 : "=r"(r[0]), "=r"(r[1]), "=r"(r[2]), "=r"(r[3]) : "r"(addr));
}
__device__ __forceinline__ void mma16816h(float* c, const uint32_t* a, uint32_t b0, uint32_t b1) {
    asm volatile(
        "mma.sync.aligned.m16n8k16.row.col.f32.f16.f16.f32 "
        "{%0,%1,%2,%3}, {%4,%5,%6,%7}, {%8,%9}, {%0,%1,%2,%3};"
        : "+f"(c[0]), "+f"(c[1]), "+f"(c[2]), "+f"(c[3])
        : "r"(a[0]), "r"(a[1]), "r"(a[2]), "r"(a[3]), "r"(b0), "r"(b1));
}
#define MMSTRIDE 72
__device__ __forceinline__ uint32_t faddr(uint32_t base, int row0, int kk, int lane) {
    return base + (uint32_t)(((row0 + (lane & 15)) * MMSTRIDE + kk * 16 + ((lane >> 4) << 3)) * 2);
}
__device__ __forceinline__ void cpa16(uint32_t dst, const void* src) {
    asm volatile("cp.async.cg.shared.global [%0], [%1], 16;"
                 :: "r"(dst), "l"(__cvta_generic_to_global(src)) : "memory");
}
__device__ __forceinline__ void cpa16z(uint32_t dst, const void* src, int bytes) {
    asm volatile("cp.async.cg.shared.global [%0], [%1], 16, %2;"
                 :: "r"(dst), "l"(__cvta_generic_to_global(src)), "r"(bytes) : "memory");
}

// ======================= convert kernels =======================
__global__ void splitcvt16_kernel(const float* __restrict__ x, __half* __restrict__ o16, int n) {
    int i = (blockIdx.x * 256 + threadIdx.x) * 4;
    if (i >= n) return;
    float4 v = *(const float4*)(x + i);
    uint2 o;
    o.x = h2pack(v.x, v.y);
    o.y = h2pack(v.z, v.w);
    *(uint2*)&o16[i] = o;
}

__global__ void wconvT16_kernel(const float* __restrict__ W, __half* __restrict__ th,
                                int K, int N) {
    __shared__ float sm[32][33];
    const int k0 = blockIdx.y * 32, n0 = blockIdx.x * 32;
    const int tx = threadIdx.x, ty = threadIdx.y;
    const int t = ty * 32 + tx;
#pragma unroll
    for (int i = 0; i < 4; i++)
        sm[ty + 8 * i][tx] = W[(size_t)(k0 + ty + 8 * i) * N + n0 + tx];
    __syncthreads();
#pragma unroll
    for (int e = 0; e < 2; e++) {
        int pid = e * 256 + t;
        int n = pid >> 4, kp = pid & 15;
        *(uint32_t*)&th[(size_t)(n0 + n) * K + k0 + 2 * kp] =
            h2pack(sm[2 * kp][n], sm[2 * kp + 1][n]);
    }
}

__global__ void vconvT16h_kernel(const __half* __restrict__ v16, __half* __restrict__ th) {
    __shared__ float sm[32][33];
    const int t0 = blockIdx.x * 32, c0 = blockIdx.y * 32;
    const int tx = threadIdx.x, ty = threadIdx.y;
    const int t = ty * 32 + tx;
#pragma unroll
    for (int i = 0; i < 4; i++)
        sm[ty + 8 * i][tx] = __half2float(v16[(size_t)(t0 + ty + 8 * i) * D + c0 + tx]);
    __syncthreads();
#pragma unroll
    for (int e = 0; e < 2; e++) {
        int pid = e * 256 + t;
        int c = pid >> 4, tp = pid & 15;
        *(uint32_t*)&th[(size_t)(c0 + c) * T + t0 + 2 * tp] =
            h2pack(sm[2 * tp][c], sm[2 * tp + 1][c]);
    }
}

// ======================= layernorm -> fp16 =======================
__global__ void ln16_kernel(const float* __restrict__ x, const float* __restrict__ g,
                            const float* __restrict__ b, __half* __restrict__ o16) {
    const int row = blockIdx.x;
    const int t = threadIdx.x;
    const float* xr = x + (size_t)row * D;
    float4 v = *(const float4*)&xr[t * 4];
    float s = v.x + v.y + v.z + v.w;
    __shared__ float red1[8], red2[8];
    s = warpSum(s);
    if ((t & 31) == 0) red1[t >> 5] = s;
    __syncthreads();
    float tot = red1[0] + red1[1] + red1[2] + red1[3] + red1[4] + red1[5] + red1[6] + red1[7];
    const float mean = tot * (1.0f / D);
    float dx = v.x - mean, dy = v.y - mean, dz = v.z - mean, dw = v.w - mean;
    float s2 = dx * dx + dy * dy + dz * dz + dw * dw;
    s2 = warpSum(s2);
    if ((t & 31) == 0) red2[t >> 5] = s2;
    __syncthreads();
    float var = (red2[0] + red2[1] + red2[2] + red2[3] + red2[4] + red2[5] + red2[6] + red2[7]) * (1.0f / D);
    const float inv = rsqrtf(var + 1e-5f);
    float4 gg = *(const float4*)&g[t * 4];
    float4 bb = *(const float4*)&b[t * 4];
    uint2 o;
    o.x = h2pack(dx * inv * gg.x + bb.x, dy * inv * gg.y + bb.y);
    o.y = h2pack(dz * inv * gg.z + bb.z, dw * inv * gg.w + bb.w);
    *(uint2*)&o16[(size_t)row * D + t * 4] = o;
}

// ======================= fp16 1-term GEMM: 128x128 tile, 2 CTAs/SM ============
// EPI bits: 1=bias, 2=relu, 4=residual, 8=fp16-out
#define H_ARR (128 * MMSTRIDE * 2)
#define H_STAGE (2 * H_ARR)
#define MMH_SMEM (2 * H_STAGE)              // 73728

__device__ __forceinline__ void mmh_load_chunk(
    const __half* __restrict__ A, const __half* __restrict__ B,
    int m0, int n0, int K, int t, uint32_t stage_base, int tid) {
    const size_t k0 = (size_t)t * 64;
#pragma unroll
    for (int e = 0; e < 8; e++) {
        int idx = e * 256 + tid;
        int arr = idx >> 10;
        int row = (idx >> 3) & 127;
        int ck  = idx & 7;
        const __half* src = (arr == 0 ? A + (size_t)(m0 + row) * K
                                      : B + (size_t)(n0 + row) * K) + k0 + ck * 8;
        cpa16(stage_base + (uint32_t)arr * H_ARR + (uint32_t)(row * 144 + ck * 16), src);
    }
    asm volatile("cp.async.commit_group;" ::: "memory");
}

template <int EPI>
__global__ void __launch_bounds__(256, 2) mmh_kernel(
    const __half* __restrict__ A, const __half* __restrict__ B,
    const float* __restrict__ bias, const float* __restrict__ Rm,
    float* __restrict__ Cf, __half* __restrict__ C16,
    int M, int N, int K) {
    extern __shared__ char smem[];
    const uint32_t sbase = smem_u32(smem);
    const int tid = threadIdx.x;
    const int wid = tid >> 5, lane = tid & 31;
    const int m0 = blockIdx.y * 128, n0 = blockIdx.x * 128;
    const int mrow = (wid & 3) * 32;
    const int nrow = (wid >> 2) * 64;

    float c[2][8][4] = {};
    const int nch = K / 64;

    mmh_load_chunk(A, B, m0, n0, K, 0, sbase, tid);

    for (int t = 0; t < nch; t++) {
        asm volatile("cp.async.wait_group 0;" ::: "memory");
        __syncthreads();
        if (t + 1 < nch)
            mmh_load_chunk(A, B, m0, n0, K, t + 1, sbase + ((t + 1) & 1) * H_STAGE, tid);
        const uint32_t sb = sbase + (t & 1) * H_STAGE;
        const uint32_t vb = sb + H_ARR;
#pragma unroll
        for (int kk = 0; kk < 4; kk++) {
            uint32_t a[2][4], b[4][4];
            ldsm_x4(a[0], faddr(sb, mrow,      kk, lane));
            ldsm_x4(a[1], faddr(sb, mrow + 16, kk, lane));
#pragma unroll
            for (int nf = 0; nf < 4; nf++)
                ldsm_x4(b[nf], faddr(vb, nrow + nf * 16, kk, lane));
#pragma unroll
            for (int mi = 0; mi < 2; mi++)
#pragma unroll
                for (int nb = 0; nb < 8; nb++) {
                    const int nf = nb >> 1, o = nb & 1;
                    mma16816h(c[mi][nb], a[mi], b[nf][o], b[nf][2 + o]);
                }
        }
    }

    const int tq = lane >> 2, tr = lane & 3;
#pragma unroll
    for (int mi = 0; mi < 2; mi++)
#pragma unroll
        for (int nb = 0; nb < 8; nb++)
#pragma unroll
            for (int hh = 0; hh < 2; hh++) {
                int gr = m0 + mrow + mi * 16 + tq + hh * 8;
                int gc = n0 + nrow + nb * 8 + tr * 2;
                float v0 = c[mi][nb][hh * 2 + 0];
                float v1 = c[mi][nb][hh * 2 + 1];
                if (EPI & 1) { v0 += bias[gc]; v1 += bias[gc + 1]; }
                if (EPI & 2) { v0 = fmaxf(v0, 0.f); v1 = fmaxf(v1, 0.f); }
                if (EPI & 4) {
                    float2 r = *(const float2*)&Rm[(size_t)gr * N + gc];
                    v0 += r.x; v1 += r.y;
                }
                if (EPI & 8) {
                    *(uint32_t*)&C16[(size_t)gr * N + gc] = h2pack(v0, v1);
                } else {
                    float2 o; o.x = v0; o.y = v1;
                    *(float2*)&Cf[(size_t)gr * N + gc] = o;
                }
            }
}

// ======================= fp16 QKV GEMM with attn-prep epilogue ================
__global__ void __launch_bounds__(256, 2) mmqkv16_kernel(
    const __half* __restrict__ A, const __half* __restrict__ B,
    const float* __restrict__ rwb, const float* __restrict__ rrb,
    __half* __restrict__ qw16, __half* __restrict__ qr16,
    __half* __restrict__ k16, __half* __restrict__ v16,
    int M, int N, int K) {
    extern __shared__ char smem[];
    const uint32_t sbase = smem_u32(smem);
    const int tid = threadIdx.x;
    const int wid = tid >> 5, lane = tid & 31;
    const int m0 = blockIdx.y * 128, n0 = blockIdx.x * 128;
    const int mrow = (wid & 3) * 32;
    const int nrow = (wid >> 2) * 64;

    float c[2][8][4] = {};
    const int nch = K / 64;

    mmh_load_chunk(A, B, m0, n0, K, 0, sbase, tid);

    for (int t = 0; t < nch; t++) {
        asm volatile("cp.async.wait_group 0;" ::: "memory");
        __syncthreads();
        if (t + 1 < nch)
            mmh_load_chunk(A, B, m0, n0, K, t + 1, sbase + ((t + 1) & 1) * H_STAGE, tid);
        const uint32_t sb = sbase + (t & 1) * H_STAGE;
        const uint32_t vb = sb + H_ARR;
#pragma unroll
        for (int kk = 0; kk < 4; kk++) {
            uint32_t a[2][4], b[4][4];
            ldsm_x4(a[0], faddr(sb, mrow,      kk, lane));
            ldsm_x4(a[1], faddr(sb, mrow + 16, kk, lane));
#pragma unroll
            for (int nf = 0; nf < 4; nf++)
                ldsm_x4(b[nf], faddr(vb, nrow + nf * 16, kk, lane));
#pragma unroll
            for (int mi = 0; mi < 2; mi++)
#pragma unroll
                for (int nb = 0; nb < 8; nb++) {
                    const int nf = nb >> 1, o = nb & 1;
                    mma16816h(c[mi][nb], a[mi], b[nf][o], b[nf][2 + o]);
                }
        }
    }

    const int tq = lane >> 2, tr = lane & 3;
#pragma unroll
    for (int mi = 0; mi < 2; mi++)
#pragma unroll
        for (int nb = 0; nb < 8; nb++)
#pragma unroll
            for (int hh = 0; hh < 2; hh++) {
                int gr = m0 + mrow + mi * 16 + tq + hh * 8;
                int gc = n0 + nrow + nb * 8 + tr * 2;
                float v0 = c[mi][nb][hh * 2 + 0];
                float v1 = c[mi][nb][hh * 2 + 1];
                if (gc < D) {
                    size_t o = (size_t)gr * D + gc;
                    *(uint32_t*)&qw16[o] = h2pack(v0 + rwb[gc], v1 + rwb[gc + 1]);
                    *(uint32_t*)&qr16[o] = h2pack(v0 + rrb[gc], v1 + rrb[gc + 1]);
                } else if (gc < 2 * D) {
                    *(uint32_t*)&k16[(size_t)gr * D + gc - D] = h2pack(v0, v1);
                } else {
                    *(uint32_t*)&v16[(size_t)gr * D + gc - 2 * D] = h2pack(v0, v1);
                }
            }
}

// ======================= fp16 1-term attention scores =======================
#define SAH 18432
#define SCH_BAND (3 * SAH)          // 55296
#define SCH_SMEM (3 * SAH + 36864)  // 92160

__global__ void __launch_bounds__(256, 2) scores16_kernel(
    const __half* __restrict__ qw, const __half* __restrict__ qr,
    const __half* __restrict__ k,  const __half* __restrict__ rk,
    float* __restrict__ sc) {
    const int h = blockIdx.z;
    const int n = blockIdx.x;
    float rf = (sqrtf(8.f * n + 1.f) - 1.f) * 0.5f;
    int iT = (int)rf;
    if ((iT + 1) * (iT + 2) / 2 <= n) iT++;
    if (iT * (iT + 1) / 2 > n) iT--;
    const int jT = n - iT * (iT + 1) / 2;
    const int i0 = iT * 128, j0 = jT * 128;
    extern __shared__ char smem[];
    const uint32_t sb = smem_u32(smem);
    const int tid = threadIdx.x;
    const int wid = tid >> 5, lane = tid & 31;
    const int mrow = (wid & 3) * 32;
    const int nrowAC = (wid >> 2) * 64;
    const int nrowQ  = (wid >> 2) * 32;
    const int pbase = T - 1 - i0 + j0 - 127;
    float* bdbuf = (float*)(smem);

#pragma unroll
    for (int e = 0; e < 12; e++) {
        int idx = e * 256 + tid;
        int arr = idx >> 10;                // 0: qw, 1: k, 2: qr
        int row = (idx >> 3) & 127;
        int ck  = idx & 7;
        const __half* src = (arr == 0) ? qw : (arr == 1) ? k : qr;
        int grow = ((arr == 1) ? j0 : i0) + row;
        cpa16(sb + (uint32_t)arr * SAH + (uint32_t)(row * 144 + ck * 16),
              src + (size_t)grow * D + h * DH + ck * 8);
    }
    asm volatile("cp.async.commit_group;" ::: "memory");
#pragma unroll
    for (int e = 0; e < 8; e++) {
        int idx = e * 256 + tid;
        int row = (idx >> 3) & 255;
        int ck  = idx & 7;
        int p = pbase + row;
        bool valid = (p >= 0 && p < T);
        size_t off = valid ? ((size_t)p * D + h * DH + ck * 8) : 0;
        cpa16z(sb + SCH_BAND + (uint32_t)(row * 144 + ck * 16), rk + off, valid ? 16 : 0);
    }
    asm volatile("cp.async.commit_group;" ::: "memory");
    asm volatile("cp.async.wait_group 1;" ::: "memory");
    __syncthreads();

    float acc[2][8][4] = {};
#pragma unroll
    for (int kk = 0; kk < 4; kk++) {
        uint32_t a[2][4], b[4][4];
        ldsm_x4(a[0], faddr(sb, mrow,      kk, lane));
        ldsm_x4(a[1], faddr(sb, mrow + 16, kk, lane));
#pragma unroll
        for (int nf = 0; nf < 4; nf++)
            ldsm_x4(b[nf], faddr(sb + SAH, nrowAC + nf * 16, kk, lane));
#pragma unroll
        for (int mi = 0; mi < 2; mi++)
#pragma unroll
            for (int nb = 0; nb < 8; nb++) {
                const int nf = nb >> 1, o = nb & 1;
                mma16816h(acc[mi][nb], a[mi], b[nf][o], b[nf][2 + o]);
            }
    }
    asm volatile("cp.async.wait_group 0;" ::: "memory");
    __syncthreads();

    const int tq = lane >> 2, tr = lane & 3;
#pragma unroll 1
    for (int q = 0; q < 4; q++) {
        float c2[2][4][4] = {};
#pragma unroll
        for (int kk = 0; kk < 4; kk++) {
            uint32_t a[2][4], b[2][4];
            ldsm_x4(a[0], faddr(sb + 2 * SAH, mrow,      kk, lane));
            ldsm_x4(a[1], faddr(sb + 2 * SAH, mrow + 16, kk, lane));
            ldsm_x4(b[0], faddr(sb + SCH_BAND, q * 64 + nrowQ,      kk, lane));
            ldsm_x4(b[1], faddr(sb + SCH_BAND, q * 64 + nrowQ + 16, kk, lane));
#pragma unroll
            for (int mi = 0; mi < 2; mi++)
#pragma unroll
                for (int nb = 0; nb < 4; nb++) {
                    const int nf = nb >> 1, o = nb & 1;
                    mma16816h(c2[mi][nb], a[mi], b[nf][o], b[nf][2 + o]);
                }
        }
        __syncthreads();
#pragma unroll
        for (int mi = 0; mi < 2; mi++)
#pragma unroll
            for (int nb = 0; nb < 4; nb++)
#pragma unroll
                for (int hh = 0; hh < 2; hh++) {
                    int di = mrow + mi * 16 + tq + hh * 8;
                    int djq = nrowQ + nb * 8 + tr * 2;
                    bdbuf[di * 66 + djq]     = c2[mi][nb][hh * 2 + 0];
                    bdbuf[di * 66 + djq + 1] = c2[mi][nb][hh * 2 + 1];
                }
        __syncthreads();
#pragma unroll
        for (int mi = 0; mi < 2; mi++)
#pragma unroll
            for (int nb = 0; nb < 8; nb++)
#pragma unroll
                for (int hh = 0; hh < 2; hh++) {
                    int di = mrow + mi * 16 + tq + hh * 8;
                    int dj = nrowAC + nb * 8 + tr * 2;
#pragma unroll
                    for (int cc = 0; cc < 2; cc++) {
                        int pl = 127 + (dj + cc) - di;
                        if ((pl >> 6) == q)
                            acc[mi][nb][hh * 2 + cc] += bdbuf[di * 66 + (pl & 63)];
                    }
                }
        __syncthreads();
    }

    const float scale = 0.125f;
#pragma unroll
    for (int mi = 0; mi < 2; mi++)
#pragma unroll
        for (int nb = 0; nb < 8; nb++)
#pragma unroll
            for (int hh = 0; hh < 2; hh++) {
                int gi = i0 + mrow + mi * 16 + tq + hh * 8;
                int gj = j0 + nrowAC + nb * 8 + tr * 2;
                float2 o;
                o.x = acc[mi][nb][hh * 2 + 0] * scale;
                o.y = acc[mi][nb][hh * 2 + 1] * scale;
                stg_cs_f2(&sc[((size_t)h * T + gi) * T + gj], o);   // streaming: read once
            }
}

// ======================= causal softmax -> fp16 probs (pad to 128) ===========
__global__ void softmax_kernel(const float* __restrict__ sc, __half* __restrict__ p16) {
    const int i = blockIdx.x;
    const int h = blockIdx.y;
    const size_t roff = ((size_t)h * T + i) * T;
    const float* row = sc + roff;
    const int t = threadIdx.x;
    const int n = i + 1;
    const int nup = (i & ~127) + 128;
    float4 v[2];
    float mx = -3.4e38f;
#pragma unroll
    for (int p = 0; p < 2; p++) {
        int j = (p * 256 + t) * 4;
        if (j < nup) {
            float4 w = ldg_cs_f4(row + j);            // streaming read (written once)
            w.x = (j + 0 < n) ? w.x : -3.4e38f;
            w.y = (j + 1 < n) ? w.y : -3.4e38f;
            w.z = (j + 2 < n) ? w.z : -3.4e38f;
            w.w = (j + 3 < n) ? w.w : -3.4e38f;
            v[p] = w;
            mx = fmaxf(mx, fmaxf(fmaxf(w.x, w.y), fmaxf(w.z, w.w)));
        } else {
            v[p].x = v[p].y = v[p].z = v[p].w = -3.4e38f;
        }
    }
    __shared__ float red1[8], red2[8];
    mx = warpMax(mx);
    if ((t & 31) == 0) red1[t >> 5] = mx;
    __syncthreads();
    mx = fmaxf(fmaxf(fmaxf(red1[0], red1[1]), fmaxf(red1[2], red1[3])),
               fmaxf(fmaxf(red1[4], red1[5]), fmaxf(red1[6], red1[7])));
    float s = 0.f;
#pragma unroll
    for (int p = 0; p < 2; p++) {
        float e0 = (v[p].x > -3.0e38f) ? __expf(v[p].x - mx) : 0.f;
        float e1 = (v[p].y > -3.0e38f) ? __expf(v[p].y - mx) : 0.f;
        float e2 = (v[p].z > -3.0e38f) ? __expf(v[p].z - mx) : 0.f;
        float e3 = (v[p].w > -3.0e38f) ? __expf(v[p].w - mx) : 0.f;
        v[p].x = e0; v[p].y = e1; v[p].z = e2; v[p].w = e3;
        s += e0 + e1 + e2 + e3;
    }
    s = warpSum(s);
    if ((t & 31) == 0) red2[t >> 5] = s;
    __syncthreads();
    float tot = red2[0] + red2[1] + red2[2] + red2[3] + red2[4] + red2[5] + red2[6] + red2[7];
    float inv = 1.0f / tot;
#pragma unroll
    for (int p = 0; p < 2; p++) {
        int j = (p * 256 + t) * 4;
        if (j < nup) {
            uint2 pu;
            pu.x = h2pack(v[p].x * inv, v[p].y * inv);
            pu.y = h2pack(v[p].z * inv, v[p].w * inv);
            *(uint2*)&p16[roff + j] = pu;
        }
    }
}

// ======================= probs layout: fp16 [h][i][j] -> f32 [i][j][h] ========
__global__ void probs_out_kernel(const __half* __restrict__ p16,
                                 float* __restrict__ out) {
    const int i = blockIdx.y;
    const int t = threadIdx.x;
    const int nup = (i & ~63) + 64;
    __shared__ float sm[16][66];
#pragma unroll 1
    for (int s = 0; s < 4; s++) {
        const int j0 = (blockIdx.x * 4 + s) * 64;
        float* dst = out + ((size_t)i * T + j0) * H;
        if (j0 < nup) {
#pragma unroll
            for (int e = 0; e < 2; e++) {
                int idx = e * 256 + t;
                int hh = idx >> 5, jp = idx & 31;
                size_t o = ((size_t)hh * T + i) * T + j0 + jp * 2;
                __half2 a = *(const __half2*)&p16[o];
                sm[hh][jp * 2]     = __half2float(a.x);
                sm[hh][jp * 2 + 1] = __half2float(a.y);
            }
            __syncthreads();
            int base = t * 4;
            float4 o4;
            o4.x = sm[(base + 0) & 15][(base + 0) >> 4];
            o4.y = sm[(base + 1) & 15][(base + 1) >> 4];
            o4.z = sm[(base + 2) & 15][(base + 2) >> 4];
            o4.w = sm[(base + 3) & 15][(base + 3) >> 4];
            stg_cs_f4(&dst[base], o4);                 // streaming: never re-read
            __syncthreads();
        } else {
            float4 z; z.x = z.y = z.z = z.w = 0.f;
            stg_cs_f4(&dst[t * 4], z);
        }
    }
}

// ======================= fp16 PV =======================
#define PVH_PARR 18432
#define PVH_VARR 9216
#define PVH_STAGE (PVH_PARR + PVH_VARR)
#define PVH_SMEM (2 * PVH_STAGE)

__device__ __forceinline__ void pvh_load_chunk(
    const __half* __restrict__ P, const __half* __restrict__ V,
    int h, int i0, int t, uint32_t stage_base, int tid) {
    const size_t j0 = (size_t)t * 64;
#pragma unroll
    for (int e = 0; e < 6; e++) {
        int idx = e * 256 + tid;
        const __half* src;
        uint32_t dst;
        if (idx < 1024) {
            int row = (idx >> 3) & 127;
            int ck  = idx & 7;
            src = P + ((size_t)h * T + i0 + row) * T + j0 + ck * 8;
            dst = stage_base + (uint32_t)(row * 144 + ck * 16);
        } else {
            int k = idx - 1024;
            int row = (k >> 3) & 63;
            int ck  = k & 7;
            src = V + (size_t)(h * DH + row) * T + j0 + ck * 8;
            dst = stage_base + PVH_PARR + (uint32_t)(row * 144 + ck * 16);
        }
        cpa16(dst, src);
    }
    asm volatile("cp.async.commit_group;" ::: "memory");
}

__global__ void __launch_bounds__(256, 2) pv16_kernel(
    const __half* __restrict__ P, const __half* __restrict__ V,
    __half* __restrict__ av16) {
    extern __shared__ char smem[];
    const uint32_t sbase = smem_u32(smem);
    const int h = blockIdx.y;
    const int i0 = (gridDim.x - 1 - blockIdx.x) * 128;
    const int tid = threadIdx.x;
    const int wid = tid >> 5, lane = tid & 31;
    const int mrow = (wid & 3) * 32;
    const int nrow = (wid >> 2) * 32;

    float c[2][4][4] = {};
    const int nch = i0 / 64 + 2;

    pvh_load_chunk(P, V, h, i0, 0, sbase, tid);

    for (int t = 0; t < nch; t++) {
        asm volatile("cp.async.wait_group 0;" ::: "memory");
        __syncthreads();
        if (t + 1 < nch)
            pvh_load_chunk(P, V, h, i0, t + 1, sbase + ((t + 1) & 1) * PVH_STAGE, tid);
        const uint32_t sb = sbase + (t & 1) * PVH_STAGE;
        const uint32_t vb = sb + PVH_PARR;
#pragma unroll
        for (int kk = 0; kk < 4; kk++) {
            uint32_t a[2][4], b[2][4];
            ldsm_x4(a[0], faddr(sb, mrow,      kk, lane));
            ldsm_x4(a[1], faddr(sb, mrow + 16, kk, lane));
            ldsm_x4(b[0], faddr(vb, nrow,      kk, lane));
            ldsm_x4(b[1], faddr(vb, nrow + 16, kk, lane));
#pragma unroll
            for (int mi = 0; mi < 2; mi++)
#pragma unroll
                for (int nb = 0; nb < 4; nb++) {
                    const int nf = nb >> 1, o = nb & 1;
                    mma16816h(c[mi][nb], a[mi], b[nf][o], b[nf][2 + o]);
                }
        }
    }

    const int tq = lane >> 2, tr = lane & 3;
#pragma unroll
    for (int mi = 0; mi < 2; mi++)
#pragma unroll
        for (int nb = 0; nb < 4; nb++)
#pragma unroll
            for (int hh = 0; hh < 2; hh++) {
                int gi = i0 + mrow + mi * 16 + tq + hh * 8;
                int gd = nrow + nb * 8 + tr * 2;
                size_t o = (size_t)gi * D + h * DH + gd;
                *(uint32_t*)&av16[o] = h2pack(c[mi][nb][hh * 2 + 0], c[mi][nb][hh * 2 + 1]);
            }
}

// ======================= host launch =======================
extern "C" void kernel_launch(void* const* d_in, const int* in_sizes, int n_in,
                              void* d_out, int out_size) {
    const float* input = (const float*)d_in[0];
    const float* pos   = (const float*)d_in[1];
    const float* rwb   = (const float*)d_in[2];
    const float* rrb   = (const float*)d_in[3];
    const float* ln1g  = (const float*)d_in[5];
    const float* ln1b  = (const float*)d_in[6];
    const float* qkvw  = (const float*)d_in[7];
    const float* rw    = (const float*)d_in[8];
    const float* ow    = (const float*)d_in[9];
    const float* ln2g  = (const float*)d_in[10];
    const float* ln2b  = (const float*)d_in[11];
    const float* ffw1  = (const float*)d_in[12];
    const float* ffb1  = (const float*)d_in[13];
    const float* ffw2  = (const float*)d_in[14];
    const float* ffb2  = (const float*)d_in[15];
    float* out = (float*)d_out;

    float *scores, *x;
    cudaGetSymbolAddress((void**)&scores, g_scores);
    cudaGetSymbolAddress((void**)&x,      g_x);
    __half *qin16, *qkvwT16, *qw16, *qr16, *k16, *v16, *rk16, *pos16, *rwT16;
    cudaGetSymbolAddress((void**)&qin16,   g_qin16);
    cudaGetSymbolAddress((void**)&qkvwT16, g_qkvwT16);
    cudaGetSymbolAddress((void**)&qw16, g_qw16);
    cudaGetSymbolAddress((void**)&qr16, g_qr16);
    cudaGetSymbolAddress((void**)&k16,  g_k16);
    cudaGetSymbolAddress((void**)&v16,  g_v16);
    cudaGetSymbolAddress((void**)&rk16, g_rk16);
    cudaGetSymbolAddress((void**)&pos16, g_pos16);
    cudaGetSymbolAddress((void**)&rwT16, g_rwT16);
    __half *p16, *vt16, *av16, *owT16, *y16, *ff16, *w1T16, *w2T16;
    cudaGetSymbolAddress((void**)&p16,   g_p16);
    cudaGetSymbolAddress((void**)&vt16,  g_vt16);
    cudaGetSymbolAddress((void**)&av16,  g_av16);
    cudaGetSymbolAddress((void**)&owT16, g_owT16);
    cudaGetSymbolAddress((void**)&y16,   g_y16);
    cudaGetSymbolAddress((void**)&ff16,  g_ff16);
    cudaGetSymbolAddress((void**)&w1T16, g_w1T16);
    cudaGetSymbolAddress((void**)&w2T16, g_w2T16);

    cudaFuncSetAttribute((const void*)mmqkv16_kernel, cudaFuncAttributeMaxDynamicSharedMemorySize, MMH_SMEM);
    cudaFuncSetAttribute((const void*)mmh_kernel<4>,  cudaFuncAttributeMaxDynamicSharedMemorySize, MMH_SMEM);
    cudaFuncSetAttribute((const void*)mmh_kernel<8>,  cudaFuncAttributeMaxDynamicSharedMemorySize, MMH_SMEM);
    cudaFuncSetAttribute((const void*)mmh_kernel<11>, cudaFuncAttributeMaxDynamicSharedMemorySize, MMH_SMEM);
    cudaFuncSetAttribute((const void*)mmh_kernel<5>,  cudaFuncAttributeMaxDynamicSharedMemorySize, MMH_SMEM);
    cudaFuncSetAttribute((const void*)scores16_kernel, cudaFuncAttributeMaxDynamicSharedMemorySize, SCH_SMEM);
    cudaFuncSetAttribute((const void*)pv16_kernel,  cudaFuncAttributeMaxDynamicSharedMemorySize, PVH_SMEM);

    const dim3 wthr(32, 8);
    const bool probs_fit =
        (long long)out_size >= (long long)T * D + (long long)H * T * T;

    ln16_kernel<<<T, 256>>>(input, ln1g, ln1b, qin16);                               // 0
    wconvT16_kernel<<<dim3(D3 / 32, D / 32), wthr>>>(qkvw, qkvwT16, D, D3);          // 1
    splitcvt16_kernel<<<(T * D) / 1024, 256>>>(pos, pos16, T * D);                   // 2
    mmqkv16_kernel<<<dim3(D3 / 128, T / 128), 256, MMH_SMEM>>>(                       // 3 (profiled)
        qin16, qkvwT16, rwb, rrb, qw16, qr16, k16, v16, T, D3, D);
    wconvT16_kernel<<<dim3(D / 32,  D / 32), wthr>>>(rw, rwT16, D, D);               // 4
    vconvT16h_kernel<<<dim3(T / 32, D / 32), wthr>>>(v16, vt16);                     // 5
    mmh_kernel<8><<<dim3(D / 128, T / 128), 256, MMH_SMEM>>>(                         // 6: rk
        pos16, rwT16, nullptr, nullptr, nullptr, rk16, T, D, D);
    wconvT16_kernel<<<dim3(D / 32,  D / 32), wthr>>>(ow, owT16, D, D);               // 7
    scores16_kernel<<<dim3(136, 1, H), 256, SCH_SMEM>>>(qw16, qr16, k16, rk16, scores);
    softmax_kernel<<<dim3(T, H), 256>>>(scores, p16);
    if (probs_fit) {
        probs_out_kernel<<<dim3(T / 256, T), 256>>>(p16, out + (size_t)T * D);
    }
    pv16_kernel<<<dim3(T / 128, H), 256, PVH_SMEM>>>(p16, vt16, av16);
    mmh_kernel<4><<<dim3(D / 128, T / 128), 256, MMH_SMEM>>>(
        av16, owT16, nullptr, input, x, nullptr, T, D, D);
    ln16_kernel<<<T, 256>>>(x, ln2g, ln2b, y16);
    wconvT16_kernel<<<dim3(DFF / 32, D / 32), wthr>>>(ffw1, w1T16, D, DFF);
    wconvT16_kernel<<<dim3(D / 32, DFF / 32), wthr>>>(ffw2, w2T16, DFF, D);
    mmh_kernel<11><<<dim3(DFF / 128, T / 128), 256, MMH_SMEM>>>(
        y16, w1T16, ffb1, nullptr, nullptr, ff16, T, DFF, D);
    mmh_kernel<5><<<dim3(D / 128, T / 128), 256, MMH_SMEM>>>(
        ff16, w2T16, ffb2, x, out, nullptr, T, D, DFF);
}